// round 1
// baseline (speedup 1.0000x reference)
#include <cuda_runtime.h>

// Problem constants
#define D   32
#define MM  64
#define DD  1024          // D*D
#define F_OUT 2080        // M*(M+1)/2
#define FP  2112          // padded to 33*64
#define NB  16            // batch
#define BK  16            // GEMM k-tile

// ---------------- scratch (static device globals; no runtime allocation) ----
__device__ float g_A_re[(size_t)FP * DD];
__device__ float g_A_im[(size_t)FP * DD];
__device__ float g_H_re[(size_t)NB * DD * DD];
__device__ float g_H_im[(size_t)NB * DD * DD];
__device__ float g_T_re[(size_t)NB * FP * DD];
__device__ float g_T_im[(size_t)NB * FP * DD];

// ---------------- kernel 1: build 2-photon SLOS amplitudes -------------------
// A[f, x*32+y] = scale * (U[j,x]U[k,32+y] + U[k,x]U[j,32+y]),  (j,k)=triu pair f
__global__ void build_amps(const float* __restrict__ U_re,
                           const float* __restrict__ U_im) {
    int f = blockIdx.x;
    int t = threadIdx.x;
    if (f >= F_OUT) {                       // zero padding rows
        for (int i = t; i < DD; i += blockDim.x) {
            g_A_re[(size_t)f * DD + i] = 0.f;
            g_A_im[(size_t)f * DD + i] = 0.f;
        }
        return;
    }
    // invert f -> (j, k), j<=k, row-major upper-triangle enumeration
    int j = 0, rem = f;
    while (rem >= MM - j) { rem -= MM - j; ++j; }
    int k = j + rem;

    __shared__ float su[4][MM];             // U row j (re,im), U row k (re,im)
    if (t < MM) {
        su[0][t] = U_re[j * MM + t];
        su[1][t] = U_im[j * MM + t];
        su[2][t] = U_re[k * MM + t];
        su[3][t] = U_im[k * MM + t];
    }
    __syncthreads();

    float sc = (j == k) ? 0.7071067811865476f : 1.0f;
    for (int i = t; i < DD; i += blockDim.x) {
        int x = i >> 5, y = i & 31;
        float ar = su[0][x],     ai = su[1][x];        // U[j,x]
        float br = su[2][D + y], bi = su[3][D + y];    // U[k,D+y]
        float cr = su[2][x],     ci = su[3][x];        // U[k,x]
        float dr = su[0][D + y], di = su[1][D + y];    // U[j,D+y]
        float re = ar * br - ai * bi + cr * dr - ci * di;
        float im = ar * bi + ai * br + cr * di + ci * dr;
        g_A_re[(size_t)f * DD + i] = sc * re;
        g_A_im[(size_t)f * DD + i] = sc * im;
    }
}

// ---------------- kernel 2: Hermitianize rho from its upper triangle ---------
// H[i][j] = rho[i][j] (i<j);  conj(rho[j][i]) (i>j);  (Re(rho_ii), 0) (i==j)
__global__ void hermitize(const float* __restrict__ rho_re,
                          const float* __restrict__ rho_im) {
    int ti = blockIdx.x, tj = blockIdx.y, b = blockIdx.z;
    if (tj < ti) return;
    __shared__ float sr[32][33];
    __shared__ float si[32][33];
    int cx = threadIdx.x, ry = threadIdx.y;
    const size_t base = (size_t)b * DD * DD;
    int r = ti * 32 + ry, c = tj * 32 + cx;
    sr[ry][cx] = rho_re[base + (size_t)r * DD + c];
    si[ry][cx] = rho_im[base + (size_t)r * DD + c];
    __syncthreads();
    if (ti == tj) {
        float re, im;
        if (ry < cx)      { re = sr[ry][cx]; im = si[ry][cx]; }
        else if (ry > cx) { re = sr[cx][ry]; im = -si[cx][ry]; }
        else              { re = sr[ry][cx]; im = 0.f; }
        g_H_re[base + (size_t)r * DD + c] = re;
        g_H_im[base + (size_t)r * DD + c] = im;
    } else {
        g_H_re[base + (size_t)r * DD + c] = sr[ry][cx];
        g_H_im[base + (size_t)r * DD + c] = si[ry][cx];
        int r2 = tj * 32 + ry, c2 = ti * 32 + cx;       // mirrored tile
        g_H_re[base + (size_t)r2 * DD + c2] = sr[cx][ry];
        g_H_im[base + (size_t)r2 * DD + c2] = -si[cx][ry];
    }
}

// ---------------- shared 3M (Karatsuba) complex MMA inner tile ---------------
// planes: 0 = re, 1 = im, 2 = re+im  (B side carries conjugation pre-folded)
// acc0 += a_re*b_re, acc1 += a_im*b_im, acc2 += (a_re+a_im)*(b_re+b_im)
// out_re = acc0 - acc1,  out_im = acc2 - acc0 - acc1
__device__ __forceinline__ void mma_tile(float (*sA)[BK][64], float (*sB)[BK][64],
                                         int ty, int tx,
                                         float (&acc0)[4][4], float (&acc1)[4][4],
                                         float (&acc2)[4][4]) {
#pragma unroll
    for (int kk = 0; kk < BK; ++kk) {
        float4 a0 = *(const float4*)&sA[0][kk][ty * 4];
        float4 a1 = *(const float4*)&sA[1][kk][ty * 4];
        float4 a2 = *(const float4*)&sA[2][kk][ty * 4];
        float4 b0 = *(const float4*)&sB[0][kk][tx * 4];
        float4 b1 = *(const float4*)&sB[1][kk][tx * 4];
        float4 b2 = *(const float4*)&sB[2][kk][tx * 4];
        float A0[4] = {a0.x, a0.y, a0.z, a0.w};
        float A1[4] = {a1.x, a1.y, a1.z, a1.w};
        float A2[4] = {a2.x, a2.y, a2.z, a2.w};
        float B0[4] = {b0.x, b0.y, b0.z, b0.w};
        float B1[4] = {b1.x, b1.y, b1.z, b1.w};
        float B2[4] = {b2.x, b2.y, b2.z, b2.w};
#pragma unroll
        for (int i = 0; i < 4; ++i)
#pragma unroll
            for (int jx = 0; jx < 4; ++jx) {
                acc0[i][jx] += A0[i] * B0[jx];
                acc1[i][jx] += A1[i] * B1[jx];
                acc2[i][jx] += A2[i] * B2[jx];
            }
    }
}

// ---------------- kernel 3: T[b] = A @ H[b]  (complex, 3M) -------------------
__global__ __launch_bounds__(256) void gemm_stage1() {
    int bn = blockIdx.x;   // H column tile (0..15)
    int bm = blockIdx.y;   // A row tile    (0..32)
    int b  = blockIdx.z;
    __shared__ __align__(16) float sA[3][BK][64];
    __shared__ __align__(16) float sB[3][BK][64];
    int tid = threadIdx.x;
    const size_t hbase = (size_t)b * DD * DD;
    const float* __restrict__ Hre = g_H_re + hbase;
    const float* __restrict__ Him = g_H_im + hbase;

    float acc0[4][4] = {}, acc1[4][4] = {}, acc2[4][4] = {};

    const int am = tid >> 2;               // A row within tile (0..63)
    const int ak = (tid & 3) << 2;         // A k-offset (0,4,8,12)
    const size_t aoff = (size_t)(bm * 64 + am) * DD + ak;
    const int hn = tid & 63;               // H col within tile
    const int hk = tid >> 6;               // 0..3
    const int tx = tid & 15, ty = tid >> 4;

    for (int k0 = 0; k0 < DD; k0 += BK) {
        // A tile: row-major global -> [k][m] smem (transpose on store)
        float4 vr = *(const float4*)(g_A_re + aoff + k0);
        float4 vi = *(const float4*)(g_A_im + aoff + k0);
        sA[0][ak + 0][am] = vr.x; sA[1][ak + 0][am] = vi.x; sA[2][ak + 0][am] = vr.x + vi.x;
        sA[0][ak + 1][am] = vr.y; sA[1][ak + 1][am] = vi.y; sA[2][ak + 1][am] = vr.y + vi.y;
        sA[0][ak + 2][am] = vr.z; sA[1][ak + 2][am] = vi.z; sA[2][ak + 2][am] = vr.z + vi.z;
        sA[0][ak + 3][am] = vr.w; sA[1][ak + 3][am] = vi.w; sA[2][ak + 3][am] = vr.w + vi.w;
        // H tile: already [k][n]
#pragma unroll
        for (int s = 0; s < 4; ++s) {
            int kk = hk * 4 + s;
            float hr = Hre[(size_t)(k0 + kk) * DD + bn * 64 + hn];
            float hi = Him[(size_t)(k0 + kk) * DD + bn * 64 + hn];
            sB[0][kk][hn] = hr; sB[1][kk][hn] = hi; sB[2][kk][hn] = hr + hi;
        }
        __syncthreads();
        mma_tile(sA, sB, ty, tx, acc0, acc1, acc2);
        __syncthreads();
    }

    const size_t tbase = (size_t)b * FP * DD;
    int f0 = bm * 64 + ty * 4, n0 = bn * 64 + tx * 4;
#pragma unroll
    for (int i = 0; i < 4; ++i) {
        float4 wre = make_float4(acc0[i][0] - acc1[i][0], acc0[i][1] - acc1[i][1],
                                 acc0[i][2] - acc1[i][2], acc0[i][3] - acc1[i][3]);
        float4 wim = make_float4(acc2[i][0] - acc0[i][0] - acc1[i][0],
                                 acc2[i][1] - acc0[i][1] - acc1[i][1],
                                 acc2[i][2] - acc0[i][2] - acc1[i][2],
                                 acc2[i][3] - acc0[i][3] - acc1[i][3]);
        *(float4*)(g_T_re + tbase + (size_t)(f0 + i) * DD + n0) = wre;
        *(float4*)(g_T_im + tbase + (size_t)(f0 + i) * DD + n0) = wim;
    }
}

// ---------------- kernel 4: C[b] = T[b] @ A^H, Hermitian-half + mirror -------
__global__ __launch_bounds__(256) void gemm_stage2(float* __restrict__ out) {
    int bg = blockIdx.x;   // g tile (0..32)
    int bf = blockIdx.y;   // f tile (0..32)
    int b  = blockIdx.z;
    if (bg < bf) return;   // Hermitian: only upper tile pairs
    __shared__ __align__(16) float sA[3][BK][64];
    __shared__ __align__(16) float sB[3][BK][64];
    int tid = threadIdx.x;
    const size_t tbase = (size_t)b * FP * DD;

    float acc0[4][4] = {}, acc1[4][4] = {}, acc2[4][4] = {};

    const int am = tid >> 2;
    const int ak = (tid & 3) << 2;
    const size_t aoff = tbase + (size_t)(bf * 64 + am) * DD + ak;   // T rows (f)
    const size_t boff = (size_t)(bg * 64 + am) * DD + ak;           // A rows (g)
    const int tx = tid & 15, ty = tid >> 4;

    for (int k0 = 0; k0 < DD; k0 += BK) {
        float4 vr = *(const float4*)(g_T_re + aoff + k0);
        float4 vi = *(const float4*)(g_T_im + aoff + k0);
        sA[0][ak + 0][am] = vr.x; sA[1][ak + 0][am] = vi.x; sA[2][ak + 0][am] = vr.x + vi.x;
        sA[0][ak + 1][am] = vr.y; sA[1][ak + 1][am] = vi.y; sA[2][ak + 1][am] = vr.y + vi.y;
        sA[0][ak + 2][am] = vr.z; sA[1][ak + 2][am] = vi.z; sA[2][ak + 2][am] = vr.z + vi.z;
        sA[0][ak + 3][am] = vr.w; sA[1][ak + 3][am] = vi.w; sA[2][ak + 3][am] = vr.w + vi.w;
        // B side = conj(A[g]):  (re, -im, re-im)
        float4 wr = *(const float4*)(g_A_re + boff + k0);
        float4 wi = *(const float4*)(g_A_im + boff + k0);
        sB[0][ak + 0][am] = wr.x; sB[1][ak + 0][am] = -wi.x; sB[2][ak + 0][am] = wr.x - wi.x;
        sB[0][ak + 1][am] = wr.y; sB[1][ak + 1][am] = -wi.y; sB[2][ak + 1][am] = wr.y - wi.y;
        sB[0][ak + 2][am] = wr.z; sB[1][ak + 2][am] = -wi.z; sB[2][ak + 2][am] = wr.z - wi.z;
        sB[0][ak + 3][am] = wr.w; sB[1][ak + 3][am] = -wi.w; sB[2][ak + 3][am] = wr.w - wi.w;
        __syncthreads();
        mma_tile(sA, sB, ty, tx, acc0, acc1, acc2);
        __syncthreads();
    }

    float2* o = (float2*)out;
    int f0 = bf * 64 + ty * 4, g0 = bg * 64 + tx * 4;
#pragma unroll
    for (int i = 0; i < 4; ++i)
#pragma unroll
        for (int jx = 0; jx < 4; ++jx) {
            int f = f0 + i, g = g0 + jx;
            if (f < F_OUT && g < F_OUT && f <= g) {
                float re = acc0[i][jx] - acc1[i][jx];
                float im = acc2[i][jx] - acc0[i][jx] - acc1[i][jx];
                if (f == g) im = 0.f;   // reference cancels diag imag exactly
                o[((size_t)b * F_OUT + f) * F_OUT + g] = make_float2(re, im);
                if (f < g)
                    o[((size_t)b * F_OUT + g) * F_OUT + f] = make_float2(re, -im);
            }
        }
}

// ---------------- launch -----------------------------------------------------
extern "C" void kernel_launch(void* const* d_in, const int* in_sizes, int n_in,
                              void* d_out, int out_size) {
    const float* rho_re = (const float*)d_in[0];
    const float* rho_im = (const float*)d_in[1];
    const float* U_re   = (const float*)d_in[2];
    const float* U_im   = (const float*)d_in[3];

    build_amps<<<FP, 256>>>(U_re, U_im);
    hermitize<<<dim3(32, 32, NB), dim3(32, 32)>>>(rho_re, rho_im);
    gemm_stage1<<<dim3(16, 33, NB), 256>>>();
    gemm_stage2<<<dim3(33, 33, NB), 256>>>((float*)d_out);
}